// round 5
// baseline (speedup 1.0000x reference)
#include <cuda_runtime.h>
#include <cuda_bf16.h>

// x:    (b=8, t=50, f=129, c1=32, c2=32) float32
// mask: (g=8, f=129) float32
// out:  (b=8, t=50, g=8, c1=32, c2=32) float32
//
// out[b,t,g,:,:] = sum_{f in band g} x[b,t,f,:,:] / count[g]
//
// DRAM-BW-bound streaming (~210 MB read + 13 MB write). Single resident wave:
// grid=800 CTAs (<= 888 concurrent slots at 6 CTAs/SM), each CTA runs exactly
// two (b,t,band-pair) tasks of near-equal size (pair bin counts 32/34/30/32).
// All CTAs co-resident + equal work + shared BW -> they finish together, no
// wave-quantization tail (the R4 kernel wasted ~10% there).

#define N_F      129
#define N_BANDS  8
#define PIX4     256        // 32*32 pixels / 4 floats
#define N_TASKS  1600       // 400 (b,t) tiles * 4 band pairs
#define GRID     800        // tasks per CTA = 2, all CTAs resident in one wave

__global__ __launch_bounds__(256, 6) void band_avg_kernel(
    const float* __restrict__ x,
    const float* __restrict__ masks,
    float* __restrict__ out)
{
    __shared__ unsigned bits[N_BANDS][5];   // ballot bitmap per band
    __shared__ int   s_start[N_BANDS], s_cnt[N_BANDS], s_contig[N_BANDS];
    __shared__ float s_inv[N_BANDS];

    const int tid  = threadIdx.x;
    const int wid  = tid >> 5;
    const int lane = tid & 31;

    // --- preamble: descriptors for ALL 8 bands, once per CTA ---
    if (wid < 5) {
        const int f = wid * 32 + lane;      // 0..159
        #pragma unroll
        for (int g = 0; g < N_BANDS; ++g) {
            bool on = (f < N_F) && (masks[g * N_F + f] > 0.5f);
            unsigned b = __ballot_sync(0xffffffffu, on);
            if (lane == 0) bits[g][wid] = b;
        }
    }
    __syncthreads();
    if (tid < N_BANDS) {
        int total = 0, first = -1, last = -1;
        #pragma unroll
        for (int w = 0; w < 5; ++w) {
            unsigned b = bits[tid][w];
            total += __popc(b);
            if (b) {
                if (first < 0) first = w * 32 + __ffs(b) - 1;
                last = w * 32 + 31 - __clz(b);
            }
        }
        s_start[tid]  = first;
        s_cnt[tid]    = total;
        s_contig[tid] = (last - first + 1 == total) ? 1 : 0;
        s_inv[tid]    = 1.0f / (float)total;
    }
    __syncthreads();

    // --- two equal-size pair-tasks per CTA ---
    #pragma unroll 1
    for (int t = 0; t < 2; ++t) {
        const int task = blockIdx.x + t * GRID;   // 0..1599
        const int gp   = task & 3;                // pair id
        const int bt   = task >> 2;               // (b,t) tile 0..399

        const float4* __restrict__ xin =
            reinterpret_cast<const float4*>(x) + (size_t)bt * (N_F * PIX4) + tid;
        float4* __restrict__ o4 =
            reinterpret_cast<float4*>(out) + (size_t)bt * (N_BANDS * PIX4) + tid;

        #pragma unroll 1
        for (int s = 0; s < 2; ++s) {
            const int   g     = s ? (N_BANDS - 1 - gp) : gp;
            const int   start = s_start[g];
            const int   c     = s_cnt[g];
            const float inv   = s_inv[g];

            float ax = 0.0f, ay = 0.0f, az = 0.0f, aw = 0.0f;

            if (s_contig[g]) {
                const float4* __restrict__ p = xin + (size_t)start * PIX4;
                #pragma unroll 4
                for (int k = 0; k < c; ++k) {
                    float4 v = __ldcs(&p[(size_t)k * PIX4]);
                    ax += v.x; ay += v.y; az += v.z; aw += v.w;
                }
            } else {
                // generic fallback: iterate bitmap (unused for reference mask)
                #pragma unroll 1
                for (int f = 0; f < N_F; ++f) {
                    if ((bits[g][f >> 5] >> (f & 31)) & 1u) {
                        float4 v = __ldcs(&xin[(size_t)f * PIX4]);
                        ax += v.x; ay += v.y; az += v.z; aw += v.w;
                    }
                }
            }

            float4 r;
            r.x = ax * inv; r.y = ay * inv; r.z = az * inv; r.w = aw * inv;
            __stcs(&o4[(size_t)g * PIX4], r);   // streaming store: spare L2
        }
    }
}

extern "C" void kernel_launch(void* const* d_in, const int* in_sizes, int n_in,
                              void* d_out, int out_size)
{
    const float* x     = (const float*)d_in[0];
    const float* masks = (const float*)d_in[1];
    if (n_in >= 2 && in_sizes[0] < in_sizes[1]) {
        x     = (const float*)d_in[1];
        masks = (const float*)d_in[0];
    }
    float* out = (float*)d_out;

    band_avg_kernel<<<GRID, 256>>>(x, masks, out);
}

// round 6
// speedup vs baseline: 1.0085x; 1.0085x over previous
#include <cuda_runtime.h>
#include <cuda_bf16.h>

// x:    (b=8, t=50, f=129, c1=32, c2=32) float32
// mask: (g=8, f=129) float32
// out:  (b=8, t=50, g=8, c1=32, c2=32) float32
//
// out[b,t,g,:,:] = sum_{f in band g} x[b,t,f,:,:] / count[g]
//
// DRAM-BW-bound streaming (~211 MB read + 13 MB write). One CTA per
// (b,t, band-pair), grid = 1600 (the R4 winner). This round: 8 CTAs/SM
// (launch_bounds(256,8), regs<=32, unroll 2, 32-bit indexing) so 64 resident
// warps hide each CTA's preamble/drain phases. Many short CTAs beat few long
// ones here (R5 experiment showed persistent CTAs regress).

#define N_F      129
#define N_BANDS  8
#define PIX4     256        // 32*32 pixels / 4 floats

__global__ __launch_bounds__(256, 8) void band_avg_kernel(
    const float* __restrict__ x,
    const float* __restrict__ masks,
    float* __restrict__ out)
{
    __shared__ unsigned bits[2][5];        // ballot bitmap per band
    __shared__ int   s_start[2], s_cnt[2], s_contig[2];
    __shared__ float s_inv[2];

    const int tid = threadIdx.x;
    const int bid = blockIdx.x;            // 0..1599
    const int gp  = bid & 3;               // pair id 0..3
    const int bt  = bid >> 2;              // (b,t) tile 0..399
    const int g0  = gp;
    const int g1  = (N_BANDS - 1) - gp;

    // --- parallel mask compaction for both bands (warps 0..4) ---
    const int wid = tid >> 5;
    if (wid < 5) {
        bool on0 = false, on1 = false;
        if (tid < N_F) {
            on0 = (masks[g0 * N_F + tid] > 0.5f);
            on1 = (masks[g1 * N_F + tid] > 0.5f);
        }
        unsigned b0 = __ballot_sync(0xffffffffu, on0);
        unsigned b1 = __ballot_sync(0xffffffffu, on1);
        if ((tid & 31) == 0) { bits[0][wid] = b0; bits[1][wid] = b1; }
    }
    __syncthreads();

    if (tid < 2) {
        int total = 0, first = -1, last = -1;
        #pragma unroll
        for (int w = 0; w < 5; ++w) {
            unsigned b = bits[tid][w];
            total += __popc(b);
            if (b) {
                if (first < 0) first = w * 32 + __ffs(b) - 1;
                last = w * 32 + 31 - __clz(b);
            }
        }
        s_start[tid]  = first;
        s_cnt[tid]    = total;
        s_contig[tid] = (last - first + 1 == total) ? 1 : 0;
        s_inv[tid]    = 1.0f / (float)total;
    }
    __syncthreads();

    // 32-bit offsets: x is 52.8M floats = 13.2M float4 -> fits int easily.
    const float4* __restrict__ xin =
        reinterpret_cast<const float4*>(x) + (bt * (N_F * PIX4) + tid);
    float4* __restrict__ o4 =
        reinterpret_cast<float4*>(out) + (bt * (N_BANDS * PIX4) + tid);

    #pragma unroll 1
    for (int s = 0; s < 2; ++s) {
        const int   g     = s ? g1 : g0;
        const int   start = s_start[s];
        const int   c     = s_cnt[s];
        const float inv   = s_inv[s];

        float ax = 0.0f, ay = 0.0f, az = 0.0f, aw = 0.0f;

        if (s_contig[s]) {
            const float4* __restrict__ p = xin + start * PIX4;
            #pragma unroll 2
            for (int k = 0; k < c; ++k) {
                float4 v = __ldcs(&p[k * PIX4]);
                ax += v.x; ay += v.y; az += v.z; aw += v.w;
            }
        } else {
            // generic fallback: iterate the bitmap (unused for reference mask)
            #pragma unroll 1
            for (int f = 0; f < N_F; ++f) {
                if ((bits[s][f >> 5] >> (f & 31)) & 1u) {
                    float4 v = __ldcs(&xin[f * PIX4]);
                    ax += v.x; ay += v.y; az += v.z; aw += v.w;
                }
            }
        }

        float4 r;
        r.x = ax * inv; r.y = ay * inv; r.z = az * inv; r.w = aw * inv;
        o4[g * PIX4] = r;
    }
}

extern "C" void kernel_launch(void* const* d_in, const int* in_sizes, int n_in,
                              void* d_out, int out_size)
{
    const float* x     = (const float*)d_in[0];
    const float* masks = (const float*)d_in[1];
    if (n_in >= 2 && in_sizes[0] < in_sizes[1]) {
        x     = (const float*)d_in[1];
        masks = (const float*)d_in[0];
    }
    float* out = (float*)d_out;

    const int n_blocks = 8 * 50 * (N_BANDS / 2);  // 1600: one per (b,t,pair)
    band_avg_kernel<<<n_blocks, 256>>>(x, masks, out);
}

// round 7
// speedup vs baseline: 1.0601x; 1.0511x over previous
#include <cuda_runtime.h>
#include <cuda_bf16.h>

// x:    (b=8, t=50, f=129, c1=32, c2=32) float32
// mask: (g=8, f=129) float32
// out:  (b=8, t=50, g=8, c1=32, c2=32) float32
//
// out[b,t,g,:,:] = sum_{f in band g} x[b,t,f,:,:] / count[g]
//
// DRAM-BW-bound streaming (~211 MB read + 13 MB write). One CTA per
// (b,t, band-pair), grid = 1600 (R4 structure — the empirical winner).
// This round: per-thread MLP = 8 (unroll 8, launch_bounds(256,4), ~48 regs)
// -> ~128 KB in flight per SM. Cross-round data shows DRAM% tracks in-flight
// bytes, not occupancy (R6: occ 80% with MLP 2 regressed to 69.6% DRAM).

#define N_F      129
#define N_BANDS  8
#define PIX4     256        // 32*32 pixels / 4 floats

__global__ __launch_bounds__(256, 4) void band_avg_kernel(
    const float* __restrict__ x,
    const float* __restrict__ masks,
    float* __restrict__ out)
{
    __shared__ unsigned bits[2][5];        // ballot bitmap per band
    __shared__ int   s_start[2], s_cnt[2], s_contig[2];
    __shared__ float s_inv[2];

    const int tid = threadIdx.x;
    const int bid = blockIdx.x;            // 0..1599
    const int gp  = bid & 3;               // pair id 0..3
    const int bt  = bid >> 2;              // (b,t) tile 0..399
    const int g0  = gp;
    const int g1  = (N_BANDS - 1) - gp;

    // --- parallel mask compaction for both bands (warps 0..4) ---
    const int wid = tid >> 5;
    if (wid < 5) {
        bool on0 = false, on1 = false;
        if (tid < N_F) {
            on0 = (masks[g0 * N_F + tid] > 0.5f);
            on1 = (masks[g1 * N_F + tid] > 0.5f);
        }
        unsigned b0 = __ballot_sync(0xffffffffu, on0);
        unsigned b1 = __ballot_sync(0xffffffffu, on1);
        if ((tid & 31) == 0) { bits[0][wid] = b0; bits[1][wid] = b1; }
    }
    __syncthreads();

    if (tid < 2) {
        int total = 0, first = -1, last = -1;
        #pragma unroll
        for (int w = 0; w < 5; ++w) {
            unsigned b = bits[tid][w];
            total += __popc(b);
            if (b) {
                if (first < 0) first = w * 32 + __ffs(b) - 1;
                last = w * 32 + 31 - __clz(b);
            }
        }
        s_start[tid]  = first;
        s_cnt[tid]    = total;
        s_contig[tid] = (last - first + 1 == total) ? 1 : 0;
        s_inv[tid]    = 1.0f / (float)total;
    }
    __syncthreads();

    const float4* __restrict__ xin =
        reinterpret_cast<const float4*>(x) + ((size_t)bt * (N_F * PIX4) + tid);
    float4* __restrict__ o4 =
        reinterpret_cast<float4*>(out) + ((size_t)bt * (N_BANDS * PIX4) + tid);

    #pragma unroll 1
    for (int s = 0; s < 2; ++s) {
        const int   g     = s ? g1 : g0;
        const int   start = s_start[s];
        const int   c     = s_cnt[s];
        const float inv   = s_inv[s];

        float ax = 0.0f, ay = 0.0f, az = 0.0f, aw = 0.0f;
        float bx = 0.0f, by = 0.0f, bz = 0.0f, bw = 0.0f;

        if (s_contig[s]) {
            const float4* __restrict__ p = xin + (size_t)start * PIX4;
            // main loop: 8 independent loads in flight per thread
            int k = 0;
            #pragma unroll 1
            for (; k + 8 <= c; k += 8) {
                float4 v0 = __ldcs(&p[(size_t)(k + 0) * PIX4]);
                float4 v1 = __ldcs(&p[(size_t)(k + 1) * PIX4]);
                float4 v2 = __ldcs(&p[(size_t)(k + 2) * PIX4]);
                float4 v3 = __ldcs(&p[(size_t)(k + 3) * PIX4]);
                float4 v4 = __ldcs(&p[(size_t)(k + 4) * PIX4]);
                float4 v5 = __ldcs(&p[(size_t)(k + 5) * PIX4]);
                float4 v6 = __ldcs(&p[(size_t)(k + 6) * PIX4]);
                float4 v7 = __ldcs(&p[(size_t)(k + 7) * PIX4]);
                ax += v0.x; ay += v0.y; az += v0.z; aw += v0.w;
                bx += v1.x; by += v1.y; bz += v1.z; bw += v1.w;
                ax += v2.x; ay += v2.y; az += v2.z; aw += v2.w;
                bx += v3.x; by += v3.y; bz += v3.z; bw += v3.w;
                ax += v4.x; ay += v4.y; az += v4.z; aw += v4.w;
                bx += v5.x; by += v5.y; bz += v5.z; bw += v5.w;
                ax += v6.x; ay += v6.y; az += v6.z; aw += v6.w;
                bx += v7.x; by += v7.y; bz += v7.z; bw += v7.w;
            }
            #pragma unroll 4
            for (; k < c; ++k) {
                float4 v = __ldcs(&p[(size_t)k * PIX4]);
                ax += v.x; ay += v.y; az += v.z; aw += v.w;
            }
        } else {
            // generic fallback: iterate the bitmap (unused for reference mask)
            #pragma unroll 1
            for (int f = 0; f < N_F; ++f) {
                if ((bits[s][f >> 5] >> (f & 31)) & 1u) {
                    float4 v = __ldcs(&xin[(size_t)f * PIX4]);
                    ax += v.x; ay += v.y; az += v.z; aw += v.w;
                }
            }
        }

        float4 r;
        r.x = (ax + bx) * inv;
        r.y = (ay + by) * inv;
        r.z = (az + bz) * inv;
        r.w = (aw + bw) * inv;
        o4[(size_t)g * PIX4] = r;
    }
}

extern "C" void kernel_launch(void* const* d_in, const int* in_sizes, int n_in,
                              void* d_out, int out_size)
{
    const float* x     = (const float*)d_in[0];
    const float* masks = (const float*)d_in[1];
    if (n_in >= 2 && in_sizes[0] < in_sizes[1]) {
        x     = (const float*)d_in[1];
        masks = (const float*)d_in[0];
    }
    float* out = (float*)d_out;

    const int n_blocks = 8 * 50 * (N_BANDS / 2);  // 1600: one per (b,t,pair)
    band_avg_kernel<<<n_blocks, 256>>>(x, masks, out);
}